// round 1
// baseline (speedup 1.0000x reference)
#include <cuda_runtime.h>
#include <cuda_bf16.h>

// Problem constants
#define T_   4
#define B_   32
#define C_   384
#define N_   256
#define TB_  128         // T_*B_
#define HEADS 8
#define CH   48          // C_/HEADS
#define BCN  3145728     // B_*C_*N_  (size_t math via casts)
#define TBCN 12582912    // T_*B_*C_*N_

// Scratch (device globals, no allocations allowed)
__device__ float g_qlin[TBCN];
__device__ float g_klin[TBCN];
__device__ float g_ybuf[TBCN];

// ---------------------------------------------------------------------------
// SGEMM with fused BatchNorm (+ optional bias) epilogue.
// out[tb, d, n] = BN( sum_c W[d,c] * X[tb, c, n]  (+ bias[d]) )
// X, out: [TB_, C_, N_] ; W: [C_, C_] row-major (d, c)
// Tile: BM=128 (d) x BN=128 (n) x BK=8 (c); 256 threads; 8x8 per thread.
// ---------------------------------------------------------------------------
#define BM 128
#define BNN 128
#define BK 8
#define TM 8
#define TN 8

__global__ __launch_bounds__(256, 2)
void gemm_bn_kernel(const float* __restrict__ X,
                    const float* __restrict__ W,
                    const float* __restrict__ gamma,
                    const float* __restrict__ beta,
                    const float* __restrict__ mean,
                    const float* __restrict__ var,
                    const float* __restrict__ bias,   // may be nullptr
                    float* __restrict__ out)
{
    const int tb    = blockIdx.z;        // 0..127
    const int dTile = blockIdx.y;        // 0..2
    const int nTile = blockIdx.x;        // 0..1
    const int d0 = dTile * BM;
    const int n0 = nTile * BNN;

    const float* Xb = X  + (size_t)tb * C_ * N_;
    float*       Ob = out + (size_t)tb * C_ * N_;

    __shared__ float As[BK][BM];
    __shared__ float Bs[BK][BNN];

    const int tid = threadIdx.x;

    // A-load mapping: 128 rows x 8 cols = 256 float4 (2 per row)
    const int aRow  = tid >> 1;          // 0..127
    const int aCol4 = (tid & 1) * 4;     // 0 or 4
    // B-load mapping: 8 rows x 128 cols = 256 float4
    const int bRow  = tid >> 5;          // 0..7
    const int bCol  = (tid & 31) * 4;    // 0..124

    const int tm0 = (tid >> 4) * TM;     // 0,8,...,120
    const int tn0 = (tid & 15) * TN;

    float acc[TM][TN];
#pragma unroll
    for (int i = 0; i < TM; i++)
#pragma unroll
        for (int j = 0; j < TN; j++) acc[i][j] = 0.f;

    for (int c0 = 0; c0 < C_; c0 += BK) {
        // Load W tile (transposed into As[k][m])
        float4 a4 = *(const float4*)(W + (size_t)(d0 + aRow) * C_ + c0 + aCol4);
        As[aCol4 + 0][aRow] = a4.x;
        As[aCol4 + 1][aRow] = a4.y;
        As[aCol4 + 2][aRow] = a4.z;
        As[aCol4 + 3][aRow] = a4.w;
        // Load X tile
        float4 b4 = *(const float4*)(Xb + (size_t)(c0 + bRow) * N_ + n0 + bCol);
        *(float4*)&Bs[bRow][bCol] = b4;
        __syncthreads();

#pragma unroll
        for (int k = 0; k < BK; k++) {
            float ar[TM], br[TN];
            float4 a0 = *(const float4*)&As[k][tm0];
            float4 a1 = *(const float4*)&As[k][tm0 + 4];
            ar[0]=a0.x; ar[1]=a0.y; ar[2]=a0.z; ar[3]=a0.w;
            ar[4]=a1.x; ar[5]=a1.y; ar[6]=a1.z; ar[7]=a1.w;
            float4 b0 = *(const float4*)&Bs[k][tn0];
            float4 b1 = *(const float4*)&Bs[k][tn0 + 4];
            br[0]=b0.x; br[1]=b0.y; br[2]=b0.z; br[3]=b0.w;
            br[4]=b1.x; br[5]=b1.y; br[6]=b1.z; br[7]=b1.w;
#pragma unroll
            for (int i = 0; i < TM; i++)
#pragma unroll
                for (int j = 0; j < TN; j++)
                    acc[i][j] = fmaf(ar[i], br[j], acc[i][j]);
        }
        __syncthreads();
    }

    // Epilogue: BN (+ bias folded)
#pragma unroll
    for (int i = 0; i < TM; i++) {
        const int d = d0 + tm0 + i;
        const float sc = gamma[d] * rsqrtf(var[d] + 1e-5f);
        float sh = beta[d] - mean[d] * sc;
        if (bias) sh = fmaf(sc, bias[d], sh);
        float* op = Ob + (size_t)d * N_ + n0 + tn0;
        float4 o0, o1;
        o0.x = fmaf(acc[i][0], sc, sh);
        o0.y = fmaf(acc[i][1], sc, sh);
        o0.z = fmaf(acc[i][2], sc, sh);
        o0.w = fmaf(acc[i][3], sc, sh);
        o1.x = fmaf(acc[i][4], sc, sh);
        o1.y = fmaf(acc[i][5], sc, sh);
        o1.z = fmaf(acc[i][6], sc, sh);
        o1.w = fmaf(acc[i][7], sc, sh);
        *(float4*)(op)     = o0;
        *(float4*)(op + 4) = o1;
    }
}

// ---------------------------------------------------------------------------
// Fused: q-LIF (vth=1) -> head-sum over Ch -> attn-LIF (vth=0.5) -> k-LIF ->
// y = attn * k_spike.  One thread per (b, head, n); block = one (b, head).
// LIF: h = v + (x - v)*0.5 ; s = (h >= vth) ; v = s ? 0 : h   (hard reset)
// ---------------------------------------------------------------------------
__global__ void attn_fuse_kernel(const float* __restrict__ qlin,
                                 const float* __restrict__ klin,
                                 float* __restrict__ y)
{
    const int bh = blockIdx.x;           // 0..255
    const int b  = bh >> 3;
    const int hd = bh & 7;
    const int n  = threadIdx.x;          // 0..255
    const size_t tstr = (size_t)BCN;

    float qs[4] = {0.f, 0.f, 0.f, 0.f};

    const size_t base = ((size_t)b * C_ + hd * CH) * N_ + n;

    // q-LIF per channel, accumulate spike counts per timestep
    for (int c = 0; c < CH; ++c) {
        const size_t idx = base + (size_t)c * N_;
        float v = 0.f;
#pragma unroll
        for (int t = 0; t < T_; ++t) {
            const float xq = qlin[idx + (size_t)t * tstr];
            const float h  = v + (xq - v) * 0.5f;
            const bool  sp = (h >= 1.0f);
            qs[t] += sp ? 1.f : 0.f;
            v = sp ? 0.f : h;
        }
    }

    // attn-LIF (vth = 0.5) on the per-head spike sums
    float a[4];
    {
        float v = 0.f;
#pragma unroll
        for (int t = 0; t < T_; ++t) {
            const float h = v + (qs[t] - v) * 0.5f;
            const bool sp = (h >= 0.5f);
            a[t] = sp ? 1.f : 0.f;
            v = sp ? 0.f : h;
        }
    }

    // k-LIF and gated output
    for (int c = 0; c < CH; ++c) {
        const size_t idx = base + (size_t)c * N_;
        float v = 0.f;
#pragma unroll
        for (int t = 0; t < T_; ++t) {
            const float xk = klin[idx + (size_t)t * tstr];
            const float h  = v + (xk - v) * 0.5f;
            const bool  sp = (h >= 1.0f);
            y[idx + (size_t)t * tstr] = (sp ? 1.f : 0.f) * a[t];
            v = sp ? 0.f : h;
        }
    }
}

// ---------------------------------------------------------------------------
// Final LIF over T on proj output -> spikes to d_out
// ---------------------------------------------------------------------------
__global__ void final_lif_kernel(const float* __restrict__ p,
                                 float* __restrict__ o)
{
    const size_t i = (size_t)blockIdx.x * blockDim.x + threadIdx.x;  // < BCN
    float v = 0.f;
#pragma unroll
    for (int t = 0; t < T_; ++t) {
        const float x = p[i + (size_t)t * BCN];
        const float h = v + (x - v) * 0.5f;
        const bool sp = (h >= 1.0f);
        o[i + (size_t)t * BCN] = sp ? 1.f : 0.f;
        v = sp ? 0.f : h;
    }
}

// ---------------------------------------------------------------------------
extern "C" void kernel_launch(void* const* d_in, const int* in_sizes, int n_in,
                              void* d_out, int out_size)
{
    const float* x        = (const float*)d_in[0];
    const float* q_w      = (const float*)d_in[1];
    const float* q_gamma  = (const float*)d_in[2];
    const float* q_beta   = (const float*)d_in[3];
    const float* q_mean   = (const float*)d_in[4];
    const float* q_var    = (const float*)d_in[5];
    const float* k_w      = (const float*)d_in[6];
    const float* k_gamma  = (const float*)d_in[7];
    const float* k_beta   = (const float*)d_in[8];
    const float* k_mean   = (const float*)d_in[9];
    const float* k_var    = (const float*)d_in[10];
    const float* p_w      = (const float*)d_in[11];
    const float* p_gamma  = (const float*)d_in[12];
    const float* p_beta   = (const float*)d_in[13];
    const float* p_mean   = (const float*)d_in[14];
    const float* p_var    = (const float*)d_in[15];
    const float* p_b      = (const float*)d_in[16];

    float *qlin, *klin, *ybuf;
    cudaGetSymbolAddress((void**)&qlin, g_qlin);
    cudaGetSymbolAddress((void**)&klin, g_klin);
    cudaGetSymbolAddress((void**)&ybuf, g_ybuf);

    dim3 grid(N_ / BNN, C_ / BM, TB_);   // (2, 3, 128)

    gemm_bn_kernel<<<grid, 256>>>(x, q_w, q_gamma, q_beta, q_mean, q_var,
                                  nullptr, qlin);
    gemm_bn_kernel<<<grid, 256>>>(x, k_w, k_gamma, k_beta, k_mean, k_var,
                                  nullptr, klin);

    attn_fuse_kernel<<<B_ * HEADS, N_>>>(qlin, klin, ybuf);

    // proj GEMM (bias folded into BN shift); reuse qlin as proj output
    gemm_bn_kernel<<<grid, 256>>>(ybuf, p_w, p_gamma, p_beta, p_mean, p_var,
                                  p_b, qlin);

    final_lif_kernel<<<BCN / 256, 256>>>(qlin, (float*)d_out);
}

// round 2
// speedup vs baseline: 1.0996x; 1.0996x over previous
#include <cuda_runtime.h>
#include <cuda_bf16.h>

// Problem constants
#define T_   4
#define B_   32
#define C_   384
#define N_   256
#define TB_  128         // T_*B_
#define HEADS 8
#define CH   48          // C_/HEADS
#define BCN  3145728     // B_*C_*N_
#define TBCN 12582912    // T_*B_*C_*N_

typedef unsigned long long ull;

// Scratch (device globals, no allocations allowed)
__device__ float g_qlin[TBCN];
__device__ float g_klin[TBCN];
__device__ float g_ybuf[TBCN];

// ---------------------------------------------------------------------------
// Packed fp32x2 helpers (sm_103a FFMA2 path, per-lane IEEE fp32 FMA)
// ---------------------------------------------------------------------------
__device__ __forceinline__ ull pack2(float x) {
    ull r;
    asm("mov.b64 %0, {%1, %1};" : "=l"(r) : "f"(x));
    return r;
}
__device__ __forceinline__ void fma2(ull& d, ull a, ull b) {
    asm("fma.rn.f32x2 %0, %1, %2, %0;" : "+l"(d) : "l"(a), "l"(b));
}
__device__ __forceinline__ float2 unpack2(ull v) {
    float2 f;
    asm("mov.b64 {%0, %1}, %2;" : "=f"(f.x), "=f"(f.y) : "l"(v));
    return f;
}

// ---------------------------------------------------------------------------
// SGEMM with fused BatchNorm (+ optional bias) epilogue, FFMA2 inner loop.
// out[tb, d, n] = BN( sum_c W[d,c] * X[tb, c, n]  (+ bias[d]) )
// Tile: BM=128 (d) x BN=128 (n) x BK=8 (c); 256 threads; 8x8 per thread.
// Double-buffered shared memory, one barrier per k-block.
// ---------------------------------------------------------------------------
#define BM 128
#define BNN 128
#define BK 8

__global__ __launch_bounds__(256, 2)
void gemm_bn_kernel(const float* __restrict__ X,
                    const float* __restrict__ W,
                    const float* __restrict__ gamma,
                    const float* __restrict__ beta,
                    const float* __restrict__ mean,
                    const float* __restrict__ var,
                    const float* __restrict__ bias,   // may be nullptr
                    float* __restrict__ out)
{
    const int tb = blockIdx.z;
    const int d0 = blockIdx.y * BM;
    const int n0 = blockIdx.x * BNN;

    const float* Xb = X   + (size_t)tb * C_ * N_;
    float*       Ob = out + (size_t)tb * C_ * N_;

    __shared__ float As[2][BK][BM];
    __shared__ float Bs[2][BK][BNN];

    const int tid = threadIdx.x;

    // A-load: 128 rows x 8 cols = 256 float4 (2 per row)
    const int aRow  = tid >> 1;
    const int aCol4 = (tid & 1) * 4;
    // B-load: 8 rows x 128 cols = 256 float4
    const int bRow  = tid >> 5;
    const int bCol  = (tid & 31) * 4;

    const int tm0 = (tid >> 4) * 8;
    const int tn0 = (tid & 15) * 8;

    // Packed accumulators: acc[i][j] holds columns {tn0+2j, tn0+2j+1} for row tm0+i
    ull acc[8][4];
#pragma unroll
    for (int i = 0; i < 8; i++)
#pragma unroll
        for (int j = 0; j < 4; j++) acc[i][j] = 0ull;

    // Preload k-block 0 into buffer 0
    {
        float4 a4 = *(const float4*)(W  + (size_t)(d0 + aRow) * C_ + aCol4);
        float4 b4 = *(const float4*)(Xb + (size_t)bRow * N_ + n0 + bCol);
        As[0][aCol4 + 0][aRow] = a4.x;
        As[0][aCol4 + 1][aRow] = a4.y;
        As[0][aCol4 + 2][aRow] = a4.z;
        As[0][aCol4 + 3][aRow] = a4.w;
        *(float4*)&Bs[0][bRow][bCol] = b4;
    }
    __syncthreads();

    int buf = 0;
    const int NKB = C_ / BK;   // 48
    for (int kb = 0; kb < NKB; ++kb) {
        const int c0n = (kb + 1) * BK;
        float4 a4n, b4n;
        const bool more = (c0n < C_);
        if (more) {
            a4n = *(const float4*)(W  + (size_t)(d0 + aRow) * C_ + c0n + aCol4);
            b4n = *(const float4*)(Xb + (size_t)(c0n + bRow) * N_ + n0 + bCol);
        }

#pragma unroll
        for (int k = 0; k < BK; k++) {
            float4 av0 = *(const float4*)&As[buf][k][tm0];
            float4 av1 = *(const float4*)&As[buf][k][tm0 + 4];
            ulonglong2 bb0 = *(const ulonglong2*)&Bs[buf][k][tn0];
            ulonglong2 bb1 = *(const ulonglong2*)&Bs[buf][k][tn0 + 4];
            const ull bp0 = bb0.x, bp1 = bb0.y, bp2 = bb1.x, bp3 = bb1.y;
            float av[8];
            av[0]=av0.x; av[1]=av0.y; av[2]=av0.z; av[3]=av0.w;
            av[4]=av1.x; av[5]=av1.y; av[6]=av1.z; av[7]=av1.w;
#pragma unroll
            for (int i = 0; i < 8; i++) {
                const ull a2 = pack2(av[i]);
                fma2(acc[i][0], a2, bp0);
                fma2(acc[i][1], a2, bp1);
                fma2(acc[i][2], a2, bp2);
                fma2(acc[i][3], a2, bp3);
            }
        }

        if (more) {
            const int nb = buf ^ 1;
            As[nb][aCol4 + 0][aRow] = a4n.x;
            As[nb][aCol4 + 1][aRow] = a4n.y;
            As[nb][aCol4 + 2][aRow] = a4n.z;
            As[nb][aCol4 + 3][aRow] = a4n.w;
            *(float4*)&Bs[nb][bRow][bCol] = b4n;
            __syncthreads();
            buf = nb;
        }
    }

    // Epilogue: BN (+ bias folded)
#pragma unroll
    for (int i = 0; i < 8; i++) {
        const int d = d0 + tm0 + i;
        const float sc = gamma[d] * rsqrtf(var[d] + 1e-5f);
        float sh = beta[d] - mean[d] * sc;
        if (bias) sh = fmaf(sc, bias[d], sh);
        float2 p0 = unpack2(acc[i][0]);
        float2 p1 = unpack2(acc[i][1]);
        float2 p2 = unpack2(acc[i][2]);
        float2 p3 = unpack2(acc[i][3]);
        float4 o0, o1;
        o0.x = fmaf(p0.x, sc, sh);
        o0.y = fmaf(p0.y, sc, sh);
        o0.z = fmaf(p1.x, sc, sh);
        o0.w = fmaf(p1.y, sc, sh);
        o1.x = fmaf(p2.x, sc, sh);
        o1.y = fmaf(p2.y, sc, sh);
        o1.z = fmaf(p3.x, sc, sh);
        o1.w = fmaf(p3.y, sc, sh);
        float* op = Ob + (size_t)d * N_ + n0 + tn0;
        *(float4*)(op)     = o0;
        *(float4*)(op + 4) = o1;
    }
}

// ---------------------------------------------------------------------------
// Fused: q-LIF (vth=1) -> head-sum over Ch -> attn-LIF (vth=0.5) -> k-LIF ->
// y = attn * k_spike.  One thread per (b, head, n); block = one (b, head).
// ---------------------------------------------------------------------------
__global__ void attn_fuse_kernel(const float* __restrict__ qlin,
                                 const float* __restrict__ klin,
                                 float* __restrict__ y)
{
    const int bh = blockIdx.x;
    const int b  = bh >> 3;
    const int hd = bh & 7;
    const int n  = threadIdx.x;
    const size_t tstr = (size_t)BCN;

    float qs[4] = {0.f, 0.f, 0.f, 0.f};
    const size_t base = ((size_t)b * C_ + hd * CH) * N_ + n;

    for (int c = 0; c < CH; ++c) {
        const size_t idx = base + (size_t)c * N_;
        float v = 0.f;
#pragma unroll
        for (int t = 0; t < T_; ++t) {
            const float xq = qlin[idx + (size_t)t * tstr];
            const float h  = v + (xq - v) * 0.5f;
            const bool  sp = (h >= 1.0f);
            qs[t] += sp ? 1.f : 0.f;
            v = sp ? 0.f : h;
        }
    }

    float a[4];
    {
        float v = 0.f;
#pragma unroll
        for (int t = 0; t < T_; ++t) {
            const float h = v + (qs[t] - v) * 0.5f;
            const bool sp = (h >= 0.5f);
            a[t] = sp ? 1.f : 0.f;
            v = sp ? 0.f : h;
        }
    }

    for (int c = 0; c < CH; ++c) {
        const size_t idx = base + (size_t)c * N_;
        float v = 0.f;
#pragma unroll
        for (int t = 0; t < T_; ++t) {
            const float xk = klin[idx + (size_t)t * tstr];
            const float h  = v + (xk - v) * 0.5f;
            const bool  sp = (h >= 1.0f);
            y[idx + (size_t)t * tstr] = (sp ? 1.f : 0.f) * a[t];
            v = sp ? 0.f : h;
        }
    }
}

// ---------------------------------------------------------------------------
// Final LIF over T on proj output -> spikes to d_out
// ---------------------------------------------------------------------------
__global__ void final_lif_kernel(const float* __restrict__ p,
                                 float* __restrict__ o)
{
    const size_t i = (size_t)blockIdx.x * blockDim.x + threadIdx.x;
    float v = 0.f;
#pragma unroll
    for (int t = 0; t < T_; ++t) {
        const float x = p[i + (size_t)t * BCN];
        const float h = v + (x - v) * 0.5f;
        const bool sp = (h >= 1.0f);
        o[i + (size_t)t * BCN] = sp ? 1.f : 0.f;
        v = sp ? 0.f : h;
    }
}

// ---------------------------------------------------------------------------
extern "C" void kernel_launch(void* const* d_in, const int* in_sizes, int n_in,
                              void* d_out, int out_size)
{
    const float* x        = (const float*)d_in[0];
    const float* q_w      = (const float*)d_in[1];
    const float* q_gamma  = (const float*)d_in[2];
    const float* q_beta   = (const float*)d_in[3];
    const float* q_mean   = (const float*)d_in[4];
    const float* q_var    = (const float*)d_in[5];
    const float* k_w      = (const float*)d_in[6];
    const float* k_gamma  = (const float*)d_in[7];
    const float* k_beta   = (const float*)d_in[8];
    const float* k_mean   = (const float*)d_in[9];
    const float* k_var    = (const float*)d_in[10];
    const float* p_w      = (const float*)d_in[11];
    const float* p_gamma  = (const float*)d_in[12];
    const float* p_beta   = (const float*)d_in[13];
    const float* p_mean   = (const float*)d_in[14];
    const float* p_var    = (const float*)d_in[15];
    const float* p_b      = (const float*)d_in[16];

    float *qlin, *klin, *ybuf;
    cudaGetSymbolAddress((void**)&qlin, g_qlin);
    cudaGetSymbolAddress((void**)&klin, g_klin);
    cudaGetSymbolAddress((void**)&ybuf, g_ybuf);

    dim3 grid(N_ / BNN, C_ / BM, TB_);   // (2, 3, 128)

    gemm_bn_kernel<<<grid, 256>>>(x, q_w, q_gamma, q_beta, q_mean, q_var,
                                  nullptr, qlin);
    gemm_bn_kernel<<<grid, 256>>>(x, k_w, k_gamma, k_beta, k_mean, k_var,
                                  nullptr, klin);

    attn_fuse_kernel<<<B_ * HEADS, N_>>>(qlin, klin, ybuf);

    gemm_bn_kernel<<<grid, 256>>>(ybuf, p_w, p_gamma, p_beta, p_mean, p_var,
                                  p_b, qlin);

    final_lif_kernel<<<BCN / 256, 256>>>(qlin, (float*)d_out);
}